// round 1
// baseline (speedup 1.0000x reference)
#include <cuda_runtime.h>
#include <math.h>

#define DEPTH   14
#define LEAVES  16384
#define NNODES  32767          // 2*LEAVES - 1
#define MEM     512
#define G3      1536           // 3*MEM
#define WORD    300
#define TAG     100
#define LEAF_IN 400            // WORD + TAG
#define CH_IN   712            // MEM + 2*TAG

// ---------------- scratch (device globals; no allocation in kernel_launch) ---
__device__ float g_states[(size_t)NNODES * MEM];        // 67 MB
__device__ float g_X[(size_t)LEAVES * CH_IN];           // 47 MB  (gathered GEMM inputs)
__device__ float g_Gi[(size_t)LEAVES * G3];             // 100 MB (input-gate preacts)
__device__ float g_Gh[(size_t)(LEAVES / 2) * G3];       // 50 MB  (hidden-gate preacts)
__device__ float g_H[(size_t)(LEAVES / 2) * MEM];       // 16 MB  (h1 / h2 per level)

__device__ __forceinline__ float sigmoidf(float x) { return 1.0f / (1.0f + expf(-x)); }

// ---------------- gathers ----------------------------------------------------
__global__ void gather_leaf(const float* __restrict__ embs, const float* __restrict__ tags) {
    int idx = blockIdx.x * blockDim.x + threadIdx.x;
    if (idx >= LEAVES * LEAF_IN) return;
    int row = idx / LEAF_IN, c = idx % LEAF_IN;
    float v = (c < WORD) ? embs[row * WORD + c]
                         : tags[(size_t)(LEAVES - 1 + row) * TAG + (c - WORD)];
    g_X[(size_t)row * LEAF_IN + c] = v;
}

// row 2i = left child of node (i+n-1), row 2i+1 = right child.
// x = cat(child_state[512], child_tag[100], parent_tag[100])
__global__ void gather_child(const float* __restrict__ tags, int n) {
    int idx = blockIdx.x * blockDim.x + threadIdx.x;
    if (idx >= 2 * n * CH_IN) return;
    int row = idx / CH_IN, c = idx % CH_IN;
    int i = row >> 1;
    int id = i + n - 1;
    int child = 2 * id + 1 + (row & 1);
    float v;
    if (c < MEM)             v = g_states[(size_t)child * MEM + c];
    else if (c < MEM + TAG)  v = tags[(size_t)child * TAG + (c - MEM)];
    else                     v = tags[(size_t)id * TAG + (c - MEM - TAG)];
    g_X[(size_t)row * CH_IN + c] = v;
}

// ---------------- tiled fp32 GEMM: C[M,1536] = X[M,Kin] @ W[1536,Kin]^T + bias
#define BM 64
#define BN 64
#define BK 16
__global__ __launch_bounds__(256)
void gemm_bias(const float* __restrict__ X, const float* __restrict__ W,
               const float* __restrict__ bias, float* __restrict__ C,
               int M, int Kin) {
    __shared__ float Xs[BK][BM + 4];
    __shared__ float Ws[BK][BN + 4];
    int bm = blockIdx.y * BM;
    int bn = blockIdx.x * BN;
    int tid = threadIdx.x;
    int tm = (tid / 16) * 4;
    int tn = (tid % 16) * 4;
    float acc[4][4] = {};
    for (int k0 = 0; k0 < Kin; k0 += BK) {
        #pragma unroll
        for (int i = tid; i < BM * BK; i += 256) {
            int r = i / BK, c = i % BK;
            int gm = bm + r, gk = k0 + c;
            Xs[c][r] = (gm < M && gk < Kin) ? X[(size_t)gm * Kin + gk] : 0.0f;
        }
        #pragma unroll
        for (int i = tid; i < BN * BK; i += 256) {
            int r = i / BK, c = i % BK;
            int gn = bn + r, gk = k0 + c;
            Ws[c][r] = (gk < Kin) ? W[(size_t)gn * Kin + gk] : 0.0f;
        }
        __syncthreads();
        #pragma unroll
        for (int k = 0; k < BK; k++) {
            float4 xv = *reinterpret_cast<const float4*>(&Xs[k][tm]);
            float4 wv = *reinterpret_cast<const float4*>(&Ws[k][tn]);
            float xa[4] = {xv.x, xv.y, xv.z, xv.w};
            float wa[4] = {wv.x, wv.y, wv.z, wv.w};
            #pragma unroll
            for (int a = 0; a < 4; a++)
                #pragma unroll
                for (int b = 0; b < 4; b++)
                    acc[a][b] += xa[a] * wa[b];
        }
        __syncthreads();
    }
    #pragma unroll
    for (int a = 0; a < 4; a++) {
        int gm = bm + tm + a;
        if (gm >= M) continue;
        #pragma unroll
        for (int b = 0; b < 4; b++) {
            int gn = bn + tn + b;
            C[(size_t)gm * G3 + gn] = acc[a][b] + bias[gn];
        }
    }
}

// ---------------- gate kernels -----------------------------------------------
// h_prev = 0 case: gh = bh vector. out[m,k] = (1-z)*n
// rowStride selects which Gi rows to read (1 for leaf, 2 for even rows = left child)
__global__ void gates_h0(const float* __restrict__ Gi, int rowStride,
                         const float* __restrict__ bh, float* __restrict__ out, int M) {
    int idx = blockIdx.x * blockDim.x + threadIdx.x;
    if (idx >= M * MEM) return;
    int m = idx / MEM, k = idx % MEM;
    const float* g = Gi + (size_t)m * rowStride * G3;
    float r  = sigmoidf(g[k] + bh[k]);
    float z  = sigmoidf(g[MEM + k] + bh[MEM + k]);
    float nn = tanhf(g[2 * MEM + k] + r * bh[2 * MEM + k]);
    out[idx] = (1.0f - z) * nn;
}

// h2 = GRU(xr, h1): gi = Gi row (2m+1), gh = Gh row m (bias included), hprev = H
__global__ void gates_h2(int n) {
    int idx = blockIdx.x * blockDim.x + threadIdx.x;
    if (idx >= n * MEM) return;
    int m = idx / MEM, k = idx % MEM;
    const float* gi = g_Gi + (size_t)(2 * m + 1) * G3;
    const float* gh = g_Gh + (size_t)m * G3;
    float hp = g_H[idx];
    float r  = sigmoidf(gi[k] + gh[k]);
    float z  = sigmoidf(gi[MEM + k] + gh[MEM + k]);
    float nn = tanhf(gi[2 * MEM + k] + r * gh[2 * MEM + k]);
    g_H[idx] = (1.0f - z) * nn + z * hp;
}

// node module: x = 0 so gi = node_bi; gh = Gh row m (node_bh included); hprev = H
__global__ void gates_node(const float* __restrict__ node_bi, int n) {
    int idx = blockIdx.x * blockDim.x + threadIdx.x;
    if (idx >= n * MEM) return;
    int m = idx / MEM, k = idx % MEM;
    const float* gh = g_Gh + (size_t)m * G3;
    float hp = g_H[idx];
    float r  = sigmoidf(node_bi[k] + gh[k]);
    float z  = sigmoidf(node_bi[MEM + k] + gh[MEM + k]);
    float nn = tanhf(node_bi[2 * MEM + k] + r * gh[2 * MEM + k]);
    g_states[(size_t)(m + n - 1) * MEM + k] = (1.0f - z) * nn + z * hp;
}

__global__ void copy_out(float* __restrict__ out) {
    int k = blockIdx.x * blockDim.x + threadIdx.x;
    if (k < MEM) out[k] = g_states[k];
}

// ---------------- host driver ------------------------------------------------
extern "C" void kernel_launch(void* const* d_in, const int* in_sizes, int n_in,
                              void* d_out, int out_size) {
    const float* embs    = (const float*)d_in[0];
    const float* tags    = (const float*)d_in[1];
    const float* leaf_Wi = (const float*)d_in[2];
    // d_in[3] leaf_Wh: unused (h=0 -> gh=bh)
    const float* leaf_bi = (const float*)d_in[4];
    const float* leaf_bh = (const float*)d_in[5];
    // d_in[6] node_Wi: unused (x=0 -> gi=node_bi)
    const float* node_Wh = (const float*)d_in[7];
    const float* node_bi = (const float*)d_in[8];
    const float* node_bh = (const float*)d_in[9];
    const float* ch_Wi   = (const float*)d_in[10];
    const float* ch_Wh   = (const float*)d_in[11];
    const float* ch_bi   = (const float*)d_in[12];
    const float* ch_bh   = (const float*)d_in[13];

    float *pX, *pGi, *pGh, *pH, *pS;
    cudaGetSymbolAddress((void**)&pX,  g_X);
    cudaGetSymbolAddress((void**)&pGi, g_Gi);
    cudaGetSymbolAddress((void**)&pGh, g_Gh);
    cudaGetSymbolAddress((void**)&pH,  g_H);
    cudaGetSymbolAddress((void**)&pS,  g_states);

    const int T = 256;
    auto gg = [](int M) { return dim3(G3 / BN, (M + BM - 1) / BM); };

    // ---- leaves ----
    gather_leaf<<<(LEAVES * LEAF_IN + T - 1) / T, T>>>(embs, tags);
    gemm_bias<<<gg(LEAVES), 256>>>(pX, leaf_Wi, leaf_bi, pGi, LEAVES, LEAF_IN);
    gates_h0<<<(LEAVES * MEM + T - 1) / T, T>>>(pGi, 1, leaf_bh,
                                                pS + (size_t)(LEAVES - 1) * MEM, LEAVES);

    // ---- internal levels, bottom-up ----
    for (int lvl = DEPTH - 1; lvl >= 0; --lvl) {
        int n = 1 << lvl;
        gather_child<<<(2 * n * CH_IN + T - 1) / T, T>>>(tags, n);
        gemm_bias<<<gg(2 * n), 256>>>(pX, ch_Wi, ch_bi, pGi, 2 * n, CH_IN);
        gates_h0<<<(n * MEM + T - 1) / T, T>>>(pGi, 2, ch_bh, pH, n);         // h1
        gemm_bias<<<gg(n), 256>>>(pH, ch_Wh, ch_bh, pGh, n, MEM);             // gh for right child
        gates_h2<<<(n * MEM + T - 1) / T, T>>>(n);                            // h2 (in-place in g_H)
        gemm_bias<<<gg(n), 256>>>(pH, node_Wh, node_bh, pGh, n, MEM);         // gh for node module
        gates_node<<<(n * MEM + T - 1) / T, T>>>(node_bi, n);                 // states[ids]
    }

    copy_out<<<2, 256>>>((float*)d_out);
}

// round 3
// speedup vs baseline: 1.7552x; 1.7552x over previous
#include <cuda_runtime.h>
#include <cstdint>
#include <math.h>

#define DEPTH   14
#define LEAVES  16384
#define NNODES  32767
#define MEM     512
#define G3      1536
#define WORD    300
#define TAG     100
#define LEAF_IN 400
#define CH_IN   712

// ---------------- scratch (device globals) -----------------------------------
__device__ float g_states[(size_t)NNODES * MEM];
__device__ float g_Gi[(size_t)LEAVES * G3];
__device__ float g_Gh[(size_t)(LEAVES / 2) * G3];
__device__ float g_H[(size_t)(LEAVES / 2) * MEM];

__device__ __forceinline__ float sigmoidf(float x) { return 1.0f / (1.0f + expf(-x)); }

__device__ __forceinline__ uint32_t f2tf32(float x) {
    uint32_t r;
    asm("cvt.rna.tf32.f32 %0, %1;" : "=r"(r) : "f"(x));
    return r;
}

__device__ __forceinline__ void mma_tf32(float* c, const uint32_t* a, const uint32_t* b) {
    asm volatile(
        "mma.sync.aligned.m16n8k8.row.col.f32.tf32.tf32.f32 "
        "{%0,%1,%2,%3}, {%4,%5,%6,%7}, {%8,%9}, {%0,%1,%2,%3};"
        : "+f"(c[0]), "+f"(c[1]), "+f"(c[2]), "+f"(c[3])
        : "r"(a[0]), "r"(a[1]), "r"(a[2]), "r"(a[3]), "r"(b[0]), "r"(b[1]));
}

// ---------------- tensor-core tf32 GEMM ---------------------------------------
// C[M, 1536] = X[M, Kreal] @ W[1536, Kreal]^T + bias ; fp32 in/out, tf32 MMA.
// mode 0: A dense (ld=Kreal); mode 1: leaf concat; mode 2: child concat.
#define BM 64
#define BN 128
#define BK 32

__global__ __launch_bounds__(256)
void gemm_mma(int mode, const float* __restrict__ A,
              const float* __restrict__ embs, const float* __restrict__ tags,
              const float* __restrict__ W, const float* __restrict__ bias,
              float* __restrict__ C, int M, int Kreal, int nlvl) {
    __shared__ float As[BM][BK + 4];   // [64][36]
    __shared__ float Bs[BN][BK + 4];   // [128][36]

    const int tid  = threadIdx.x;
    const int wid  = tid >> 5, lane = tid & 31;
    const int gID  = lane >> 2, tq = lane & 3;
    const int wm   = (wid >> 2) * 32;       // warp row offset within block (0/32)
    const int wn   = (wid & 3) * 32;        // warp col offset within block (0..96)
    const int bm   = blockIdx.y * BM;
    const int bn   = blockIdx.x * BN;

    float acc[2][4][4];
    #pragma unroll
    for (int i = 0; i < 2; i++)
        #pragma unroll
        for (int j = 0; j < 4; j++)
            #pragma unroll
            for (int k = 0; k < 4; k++) acc[i][j][k] = 0.0f;

    const int NC = (Kreal + BK - 1) / BK;
    const float4 z4 = make_float4(0.f, 0.f, 0.f, 0.f);

    for (int kc = 0; kc < NC; kc++) {
        const int kbase = kc * BK;
        // ---- load A tile (64x32), 2 float4 per thread, gather fused ----
        #pragma unroll
        for (int it = 0; it < 2; it++) {
            int idx = tid + it * 256;
            int r = idx >> 3, cq = (idx & 7) * 4;
            int gm = bm + r, c4 = kbase + cq;
            float4 v = z4;
            if (mode == 0) {
                if (gm < M && c4 < Kreal)
                    v = *reinterpret_cast<const float4*>(A + (size_t)gm * Kreal + c4);
            } else if (mode == 1) {
                if (c4 < WORD)
                    v = *reinterpret_cast<const float4*>(embs + (size_t)gm * WORD + c4);
                else if (c4 < LEAF_IN)
                    v = *reinterpret_cast<const float4*>(tags + (size_t)(LEAVES - 1 + gm) * TAG + (c4 - WORD));
            } else {
                if (gm < M) {
                    int i = gm >> 1;
                    int pid = i + nlvl - 1;
                    int ch = 2 * pid + 1 + (gm & 1);
                    if (c4 < MEM)
                        v = *reinterpret_cast<const float4*>(g_states + (size_t)ch * MEM + c4);
                    else if (c4 < MEM + TAG)
                        v = *reinterpret_cast<const float4*>(tags + (size_t)ch * TAG + (c4 - MEM));
                    else if (c4 < CH_IN)
                        v = *reinterpret_cast<const float4*>(tags + (size_t)pid * TAG + (c4 - MEM - TAG));
                }
            }
            As[r][cq + 0] = __uint_as_float(f2tf32(v.x));
            As[r][cq + 1] = __uint_as_float(f2tf32(v.y));
            As[r][cq + 2] = __uint_as_float(f2tf32(v.z));
            As[r][cq + 3] = __uint_as_float(f2tf32(v.w));
        }
        // ---- load B tile (128x32), 4 float4 per thread ----
        #pragma unroll
        for (int it = 0; it < 4; it++) {
            int idx = tid + it * 256;
            int r = idx >> 3, cq = (idx & 7) * 4;
            int gn = bn + r, c4 = kbase + cq;
            float4 v = (c4 < Kreal)
                ? *reinterpret_cast<const float4*>(W + (size_t)gn * Kreal + c4) : z4;
            Bs[r][cq + 0] = __uint_as_float(f2tf32(v.x));
            Bs[r][cq + 1] = __uint_as_float(f2tf32(v.y));
            Bs[r][cq + 2] = __uint_as_float(f2tf32(v.z));
            Bs[r][cq + 3] = __uint_as_float(f2tf32(v.w));
        }
        __syncthreads();

        // ---- 4 k8-steps of m16n8k8 ----
        #pragma unroll
        for (int k8 = 0; k8 < 4; k8++) {
            const int kb = k8 * 8;
            uint32_t afr[2][4], bfr[4][2];
            #pragma unroll
            for (int mt = 0; mt < 2; mt++) {
                int r0 = wm + mt * 16 + gID;
                afr[mt][0] = __float_as_uint(As[r0][kb + tq]);
                afr[mt][1] = __float_as_uint(As[r0 + 8][kb + tq]);
                afr[mt][2] = __float_as_uint(As[r0][kb + tq + 4]);
                afr[mt][3] = __float_as_uint(As[r0 + 8][kb + tq + 4]);
            }
            #pragma unroll
            for (int nt = 0; nt < 4; nt++) {
                int n0 = wn + nt * 8 + gID;
                bfr[nt][0] = __float_as_uint(Bs[n0][kb + tq]);
                bfr[nt][1] = __float_as_uint(Bs[n0][kb + tq + 4]);
            }
            #pragma unroll
            for (int mt = 0; mt < 2; mt++)
                #pragma unroll
                for (int nt = 0; nt < 4; nt++)
                    mma_tf32(acc[mt][nt], afr[mt], bfr[nt]);
        }
        __syncthreads();
    }

    // ---- epilogue: acc + bias -> C ----
    #pragma unroll
    for (int mt = 0; mt < 2; mt++) {
        int r0 = bm + wm + mt * 16 + gID;
        int r1 = r0 + 8;
        #pragma unroll
        for (int nt = 0; nt < 4; nt++) {
            int c = bn + wn + nt * 8 + 2 * tq;
            float b0 = bias[c], b1 = bias[c + 1];
            if (r0 < M) {
                C[(size_t)r0 * G3 + c]     = acc[mt][nt][0] + b0;
                C[(size_t)r0 * G3 + c + 1] = acc[mt][nt][1] + b1;
            }
            if (r1 < M) {
                C[(size_t)r1 * G3 + c]     = acc[mt][nt][2] + b0;
                C[(size_t)r1 * G3 + c + 1] = acc[mt][nt][3] + b1;
            }
        }
    }
}

// ---------------- gate kernels -----------------------------------------------
__global__ void gates_h0(const float* __restrict__ Gi, int rowStride,
                         const float* __restrict__ bh, float* __restrict__ out, int M) {
    int idx = blockIdx.x * blockDim.x + threadIdx.x;
    if (idx >= M * MEM) return;
    int m = idx / MEM, k = idx % MEM;
    const float* g = Gi + (size_t)m * rowStride * G3;
    float r  = sigmoidf(g[k] + bh[k]);
    float z  = sigmoidf(g[MEM + k] + bh[MEM + k]);
    float nn = tanhf(g[2 * MEM + k] + r * bh[2 * MEM + k]);
    out[idx] = (1.0f - z) * nn;
}

__global__ void gates_h2(int n) {
    int idx = blockIdx.x * blockDim.x + threadIdx.x;
    if (idx >= n * MEM) return;
    int m = idx / MEM, k = idx % MEM;
    const float* gi = g_Gi + (size_t)(2 * m + 1) * G3;
    const float* gh = g_Gh + (size_t)m * G3;
    float hp = g_H[idx];
    float r  = sigmoidf(gi[k] + gh[k]);
    float z  = sigmoidf(gi[MEM + k] + gh[MEM + k]);
    float nn = tanhf(gi[2 * MEM + k] + r * gh[2 * MEM + k]);
    g_H[idx] = (1.0f - z) * nn + z * hp;
}

__global__ void gates_node(const float* __restrict__ node_bi, int n) {
    int idx = blockIdx.x * blockDim.x + threadIdx.x;
    if (idx >= n * MEM) return;
    int m = idx / MEM, k = idx % MEM;
    const float* gh = g_Gh + (size_t)m * G3;
    float hp = g_H[idx];
    float r  = sigmoidf(node_bi[k] + gh[k]);
    float z  = sigmoidf(node_bi[MEM + k] + gh[MEM + k]);
    float nn = tanhf(node_bi[2 * MEM + k] + r * gh[2 * MEM + k]);
    g_states[(size_t)(m + n - 1) * MEM + k] = (1.0f - z) * nn + z * hp;
}

__global__ void copy_out(float* __restrict__ out) {
    int k = blockIdx.x * blockDim.x + threadIdx.x;
    if (k < MEM) out[k] = g_states[k];
}

// ---------------- host driver ------------------------------------------------
extern "C" void kernel_launch(void* const* d_in, const int* in_sizes, int n_in,
                              void* d_out, int out_size) {
    const float* embs    = (const float*)d_in[0];
    const float* tags    = (const float*)d_in[1];
    const float* leaf_Wi = (const float*)d_in[2];
    const float* leaf_bi = (const float*)d_in[4];
    const float* leaf_bh = (const float*)d_in[5];
    const float* node_Wh = (const float*)d_in[7];
    const float* node_bi = (const float*)d_in[8];
    const float* node_bh = (const float*)d_in[9];
    const float* ch_Wi   = (const float*)d_in[10];
    const float* ch_Wh   = (const float*)d_in[11];
    const float* ch_bi   = (const float*)d_in[12];
    const float* ch_bh   = (const float*)d_in[13];

    float *pGi, *pGh, *pH, *pS;
    cudaGetSymbolAddress((void**)&pGi, g_Gi);
    cudaGetSymbolAddress((void**)&pGh, g_Gh);
    cudaGetSymbolAddress((void**)&pH,  g_H);
    cudaGetSymbolAddress((void**)&pS,  g_states);

    const int T = 256;
    auto grid = [](int M) { return dim3(G3 / BN, (M + BM - 1) / BM); };

    // ---- leaves ----
    gemm_mma<<<grid(LEAVES), 256>>>(1, nullptr, embs, tags,
                                    leaf_Wi, leaf_bi, pGi, LEAVES, LEAF_IN, 0);
    gates_h0<<<(LEAVES * MEM + T - 1) / T, T>>>(pGi, 1, leaf_bh,
                                                pS + (size_t)(LEAVES - 1) * MEM, LEAVES);

    // ---- internal levels, bottom-up ----
    for (int lvl = DEPTH - 1; lvl >= 0; --lvl) {
        int n = 1 << lvl;
        gemm_mma<<<grid(2 * n), 256>>>(2, nullptr, embs, tags,
                                       ch_Wi, ch_bi, pGi, 2 * n, CH_IN, n);
        gates_h0<<<(n * MEM + T - 1) / T, T>>>(pGi, 2, ch_bh, pH, n);
        gemm_mma<<<grid(n), 256>>>(0, pH, embs, tags,
                                   ch_Wh, ch_bh, pGh, n, MEM, 0);
        gates_h2<<<(n * MEM + T - 1) / T, T>>>(n);
        gemm_mma<<<grid(n), 256>>>(0, pH, embs, tags,
                                   node_Wh, node_bh, pGh, n, MEM, 0);
        gates_node<<<(n * MEM + T - 1) / T, T>>>(node_bi, n);
    }

    copy_out<<<2, 256>>>((float*)d_out);
}

// round 4
// speedup vs baseline: 2.4173x; 1.3772x over previous
#include <cuda_runtime.h>
#include <cstdint>
#include <math.h>

#define DEPTH   14
#define LEAVES  16384
#define NNODES  32767
#define MEM     512
#define G3      1536
#define WORD    300
#define TAG     100
#define LEAF_IN 400
#define CH_IN   712

// ---------------- scratch (device globals) -----------------------------------
__device__ float g_states[(size_t)NNODES * MEM];
__device__ float g_Gi[(size_t)LEAVES * G3];           // right-child preacts (odd rows)
__device__ float g_H[(size_t)(LEAVES / 2) * MEM];     // h1
__device__ float g_H2[(size_t)(LEAVES / 2) * MEM];    // h2

__device__ __forceinline__ float sigmoidf(float x) { return 1.0f / (1.0f + expf(-x)); }

__device__ __forceinline__ uint32_t f2tf32(float x) {
    uint32_t r;
    asm("cvt.rna.tf32.f32 %0, %1;" : "=r"(r) : "f"(x));
    return r;
}
__device__ __forceinline__ void mma_tf32(float* c, const uint32_t* a, const uint32_t* b) {
    asm volatile(
        "mma.sync.aligned.m16n8k8.row.col.f32.tf32.tf32.f32 "
        "{%0,%1,%2,%3}, {%4,%5,%6,%7}, {%8,%9}, {%0,%1,%2,%3};"
        : "+f"(c[0]), "+f"(c[1]), "+f"(c[2]), "+f"(c[3])
        : "r"(a[0]), "r"(a[1]), "r"(a[2]), "r"(a[3]), "r"(b[0]), "r"(b[1]));
}

// ---------------- fused GEMM + GRU-gate kernel ---------------------------------
// Computes, for a 64-row x 64-gate-col tile, all three gate preacts
// (B tile = W rows {k, 512+k, 1024+k}) and applies the GRU gate math in the
// epilogue. MODE: 0=leaf, 1=ch_Wi (h1 even rows / gi odd rows), 2=ch_Wh (h2),
// 3=node_Wh (states).
#define BK   32
#define AST  36                    // padded row stride
#define TA   (64 * AST)            // 2304 floats
#define TB   (192 * AST)           // 6912 floats
#define SMEM_SZ ((2 * TA + 2 * TB) * 4)   // 73728 bytes

template<int MODE>
__global__ __launch_bounds__(256)
void gemm_gru(const float* __restrict__ embs, const float* __restrict__ tags,
              const float* __restrict__ W, const float* __restrict__ bi,
              const float* __restrict__ bh, int M, int Kreal, int nlvl) {
    extern __shared__ float sm[];
    const int tid  = threadIdx.x;
    const int lane = tid & 31;
    const int wid  = tid >> 5;
    const int gID  = lane >> 2, tq = lane & 3;
    const int wmRow = (wid >> 2) * 32;     // 0 / 32
    const int wk    = (wid & 3) * 16;      // k-slice within 64 gate cols
    const int gk0   = blockIdx.x * 64;     // gate-col base (0..448)
    const int bm    = blockIdx.y * 64;

    float acc[2][6][4];                    // [mt][gate*2+kt][frag]
    #pragma unroll
    for (int a = 0; a < 2; a++)
        #pragma unroll
        for (int b = 0; b < 6; b++)
            #pragma unroll
            for (int c = 0; c < 4; c++) acc[a][b][c] = 0.0f;

    const int NC = (Kreal + BK - 1) / BK;
    const float4 z4 = make_float4(0.f, 0.f, 0.f, 0.f);
    float4 av[2], bv[6];

    auto loadA = [&](int kc) {
        #pragma unroll
        for (int it = 0; it < 2; it++) {
            int idx = tid + it * 256;
            int r = idx >> 3, cq = (idx & 7) * 4;
            int gm = bm + r, c4 = kc * BK + cq;
            float4 v = z4;
            if (MODE == 0) {
                if (gm < M) {
                    if (c4 < WORD)
                        v = *reinterpret_cast<const float4*>(embs + (size_t)gm * WORD + c4);
                    else if (c4 < LEAF_IN)
                        v = *reinterpret_cast<const float4*>(tags + (size_t)(LEAVES - 1 + gm) * TAG + (c4 - WORD));
                }
            } else if (MODE == 1) {
                if (gm < M) {
                    int pid = (gm >> 1) + nlvl - 1;
                    int ch  = 2 * pid + 1 + (gm & 1);
                    if (c4 < MEM)
                        v = *reinterpret_cast<const float4*>(g_states + (size_t)ch * MEM + c4);
                    else if (c4 < MEM + TAG)
                        v = *reinterpret_cast<const float4*>(tags + (size_t)ch * TAG + (c4 - MEM));
                    else if (c4 < CH_IN)
                        v = *reinterpret_cast<const float4*>(tags + (size_t)pid * TAG + (c4 - MEM - TAG));
                }
            } else {
                const float* src = (MODE == 2) ? g_H : g_H2;
                if (gm < M && c4 < MEM)
                    v = *reinterpret_cast<const float4*>(src + (size_t)gm * MEM + c4);
            }
            av[it] = v;
        }
    };
    auto loadB = [&](int kc) {
        #pragma unroll
        for (int it = 0; it < 6; it++) {
            int idx = tid + it * 256;
            int r = idx >> 3, cq = (idx & 7) * 4;
            int g = r >> 6, kcol = r & 63;
            int grow = g * MEM + gk0 + kcol;
            int c4 = kc * BK + cq;
            bv[it] = (c4 < Kreal)
                ? *reinterpret_cast<const float4*>(W + (size_t)grow * Kreal + c4) : z4;
        }
    };
    auto storeA = [&](int buf) {
        float* base = sm + buf * TA;
        #pragma unroll
        for (int it = 0; it < 2; it++) {
            int idx = tid + it * 256;
            int r = idx >> 3, cq = (idx & 7) * 4;
            float* d = base + r * AST + cq;
            d[0] = __uint_as_float(f2tf32(av[it].x));
            d[1] = __uint_as_float(f2tf32(av[it].y));
            d[2] = __uint_as_float(f2tf32(av[it].z));
            d[3] = __uint_as_float(f2tf32(av[it].w));
        }
    };
    auto storeB = [&](int buf) {
        float* base = sm + 2 * TA + buf * TB;
        #pragma unroll
        for (int it = 0; it < 6; it++) {
            int idx = tid + it * 256;
            int r = idx >> 3, cq = (idx & 7) * 4;
            float* d = base + r * AST + cq;
            d[0] = __uint_as_float(f2tf32(bv[it].x));
            d[1] = __uint_as_float(f2tf32(bv[it].y));
            d[2] = __uint_as_float(f2tf32(bv[it].z));
            d[3] = __uint_as_float(f2tf32(bv[it].w));
        }
    };

    // prologue
    loadA(0); loadB(0); storeA(0); storeB(0);
    __syncthreads();

    for (int kc = 0; kc < NC; kc++) {
        const int cur = kc & 1;
        if (kc + 1 < NC) { loadA(kc + 1); loadB(kc + 1); }
        const float* At = sm + cur * TA;
        const float* Bt = sm + 2 * TA + cur * TB;
        #pragma unroll
        for (int k8 = 0; k8 < 4; k8++) {
            const int kb = k8 * 8;
            uint32_t afr[2][4], bfr[6][2];
            #pragma unroll
            for (int mt = 0; mt < 2; mt++) {
                const float* p = At + (wmRow + mt * 16 + gID) * AST + kb;
                afr[mt][0] = __float_as_uint(p[tq]);
                afr[mt][1] = __float_as_uint(p[8 * AST + tq]);
                afr[mt][2] = __float_as_uint(p[tq + 4]);
                afr[mt][3] = __float_as_uint(p[8 * AST + tq + 4]);
            }
            #pragma unroll
            for (int t = 0; t < 6; t++) {
                const float* p = Bt + ((t >> 1) * 64 + wk + (t & 1) * 8 + gID) * AST + kb;
                bfr[t][0] = __float_as_uint(p[tq]);
                bfr[t][1] = __float_as_uint(p[tq + 4]);
            }
            #pragma unroll
            for (int mt = 0; mt < 2; mt++)
                #pragma unroll
                for (int t = 0; t < 6; t++)
                    mma_tf32(acc[mt][t], afr[mt], bfr[t]);
        }
        if (kc + 1 < NC) { storeA(1 - cur); storeB(1 - cur); }
        __syncthreads();
    }

    // ---- fused epilogue: gate math per (row, kcol) ----
    #pragma unroll
    for (int mt = 0; mt < 2; mt++) {
        #pragma unroll
        for (int kt = 0; kt < 2; kt++) {
            #pragma unroll
            for (int j = 0; j < 4; j++) {
                int row = bm + wmRow + mt * 16 + gID + (j >> 1) * 8;
                if (row >= M) continue;
                int kcol = gk0 + wk + kt * 8 + 2 * tq + (j & 1);
                float aR = acc[mt][kt][j];
                float aZ = acc[mt][2 + kt][j];
                float aN = acc[mt][4 + kt][j];
                if (MODE == 0) {
                    float giR = aR + bi[kcol], giZ = aZ + bi[MEM + kcol], giN = aN + bi[2 * MEM + kcol];
                    float r  = sigmoidf(giR + bh[kcol]);
                    float z  = sigmoidf(giZ + bh[MEM + kcol]);
                    float nn = tanhf(giN + r * bh[2 * MEM + kcol]);
                    g_states[(size_t)(LEAVES - 1 + row) * MEM + kcol] = (1.0f - z) * nn;
                } else if (MODE == 1) {
                    float giR = aR + bi[kcol], giZ = aZ + bi[MEM + kcol], giN = aN + bi[2 * MEM + kcol];
                    if ((row & 1) == 0) {
                        float r  = sigmoidf(giR + bh[kcol]);
                        float z  = sigmoidf(giZ + bh[MEM + kcol]);
                        float nn = tanhf(giN + r * bh[2 * MEM + kcol]);
                        g_H[(size_t)(row >> 1) * MEM + kcol] = (1.0f - z) * nn;
                    } else {
                        float* d = g_Gi + (size_t)row * G3;
                        d[kcol] = giR; d[MEM + kcol] = giZ; d[2 * MEM + kcol] = giN;
                    }
                } else if (MODE == 2) {
                    float ghR = aR + bh[kcol], ghZ = aZ + bh[MEM + kcol], ghN = aN + bh[2 * MEM + kcol];
                    const float* gi = g_Gi + (size_t)(2 * row + 1) * G3;
                    float r  = sigmoidf(gi[kcol] + ghR);
                    float z  = sigmoidf(gi[MEM + kcol] + ghZ);
                    float nn = tanhf(gi[2 * MEM + kcol] + r * ghN);
                    g_H2[(size_t)row * MEM + kcol] =
                        (1.0f - z) * nn + z * g_H[(size_t)row * MEM + kcol];
                } else {
                    float ghR = aR + bh[kcol], ghZ = aZ + bh[MEM + kcol], ghN = aN + bh[2 * MEM + kcol];
                    float r  = sigmoidf(bi[kcol] + ghR);
                    float z  = sigmoidf(bi[MEM + kcol] + ghZ);
                    float nn = tanhf(bi[2 * MEM + kcol] + r * ghN);
                    g_states[(size_t)(row + nlvl - 1) * MEM + kcol] =
                        (1.0f - z) * nn + z * g_H2[(size_t)row * MEM + kcol];
                }
            }
        }
    }
}

__global__ void copy_out(float* __restrict__ out) {
    int k = blockIdx.x * blockDim.x + threadIdx.x;
    if (k < MEM) out[k] = g_states[k];
}

// ---------------- host driver ------------------------------------------------
extern "C" void kernel_launch(void* const* d_in, const int* in_sizes, int n_in,
                              void* d_out, int out_size) {
    const float* embs    = (const float*)d_in[0];
    const float* tags    = (const float*)d_in[1];
    const float* leaf_Wi = (const float*)d_in[2];
    const float* leaf_bi = (const float*)d_in[4];
    const float* leaf_bh = (const float*)d_in[5];
    const float* node_Wh = (const float*)d_in[7];
    const float* node_bi = (const float*)d_in[8];
    const float* node_bh = (const float*)d_in[9];
    const float* ch_Wi   = (const float*)d_in[10];
    const float* ch_Wh   = (const float*)d_in[11];
    const float* ch_bi   = (const float*)d_in[12];
    const float* ch_bh   = (const float*)d_in[13];

    cudaFuncSetAttribute(gemm_gru<0>, cudaFuncAttributeMaxDynamicSharedMemorySize, SMEM_SZ);
    cudaFuncSetAttribute(gemm_gru<1>, cudaFuncAttributeMaxDynamicSharedMemorySize, SMEM_SZ);
    cudaFuncSetAttribute(gemm_gru<2>, cudaFuncAttributeMaxDynamicSharedMemorySize, SMEM_SZ);
    cudaFuncSetAttribute(gemm_gru<3>, cudaFuncAttributeMaxDynamicSharedMemorySize, SMEM_SZ);

    auto grid = [](int M) { return dim3(MEM / 64, (M + 63) / 64); };

    // ---- leaves: GEMM + gates fused, writes leaf states directly ----
    gemm_gru<0><<<grid(LEAVES), 256, SMEM_SZ>>>(embs, tags, leaf_Wi, leaf_bi, leaf_bh,
                                                LEAVES, LEAF_IN, 0);

    // ---- internal levels, bottom-up: 3 fused kernels per level ----
    for (int lvl = DEPTH - 1; lvl >= 0; --lvl) {
        int n = 1 << lvl;
        gemm_gru<1><<<grid(2 * n), 256, SMEM_SZ>>>(embs, tags, ch_Wi, ch_bi, ch_bh,
                                                   2 * n, CH_IN, n);
        gemm_gru<2><<<grid(n), 256, SMEM_SZ>>>(embs, tags, ch_Wh, ch_bi, ch_bh,
                                               n, MEM, n);
        gemm_gru<3><<<grid(n), 256, SMEM_SZ>>>(embs, tags, node_Wh, node_bi, node_bh,
                                               n, MEM, n);
    }

    copy_out<<<2, 256>>>((float*)d_out);
}

// round 5
// speedup vs baseline: 2.6677x; 1.1036x over previous
#include <cuda_runtime.h>
#include <cstdint>
#include <math.h>

#define DEPTH   14
#define LEAVES  16384
#define NNODES  32767
#define MEM     512
#define G3      1536
#define WORD    300
#define TAG     100
#define LEAF_IN 400
#define CH_IN   712

// ---------------- scratch (device globals) -----------------------------------
__device__ float g_states[(size_t)NNODES * MEM];
__device__ float g_Gi[(size_t)LEAVES * G3];           // right-child preacts (odd rows)
__device__ float g_H[(size_t)(LEAVES / 2) * MEM];     // h1
__device__ float g_H2[(size_t)(LEAVES / 2) * MEM];    // h2

__device__ __forceinline__ float sigmoidf(float x) { return 1.0f / (1.0f + expf(-x)); }

__device__ __forceinline__ uint32_t f2tf32(float x) {
    uint32_t r;
    asm("cvt.rna.tf32.f32 %0, %1;" : "=r"(r) : "f"(x));
    return r;
}
__device__ __forceinline__ void mma_tf32(float* c, const uint32_t* a, const uint32_t* b) {
    asm volatile(
        "mma.sync.aligned.m16n8k8.row.col.f32.tf32.tf32.f32 "
        "{%0,%1,%2,%3}, {%4,%5,%6,%7}, {%8,%9}, {%0,%1,%2,%3};"
        : "+f"(c[0]), "+f"(c[1]), "+f"(c[2]), "+f"(c[3])
        : "r"(a[0]), "r"(a[1]), "r"(a[2]), "r"(a[3]), "r"(b[0]), "r"(b[1]));
}
__device__ __forceinline__ void ldsm4(uint32_t* r, uint32_t addr) {
    asm volatile("ldmatrix.sync.aligned.m8n8.x4.shared.b16 {%0,%1,%2,%3}, [%4];"
                 : "=r"(r[0]), "=r"(r[1]), "=r"(r[2]), "=r"(r[3]) : "r"(addr));
}
__device__ __forceinline__ uint32_t smem_u32(const void* p) {
    uint32_t a;
    asm("{ .reg .u64 t; cvta.to.shared.u64 t, %1; cvt.u32.u64 %0, t; }" : "=r"(a) : "l"(p));
    return a;
}

// ---------------- fused GEMM + GRU-gate kernel ---------------------------------
// 64-row x 64-gate-col tile; B tile = W rows {k, 512+k, 1024+k} (192 rows).
// MODE: 0=leaf, 1=ch_Wi (h1 even rows / gi odd rows), 2=ch_Wh (h2), 3=node_Wh.
#define BK   32
#define AST  36                    // padded row stride (floats)
#define TA   (64 * AST)
#define TB   (192 * AST)
#define SMEM_SZ ((2 * TA + 2 * TB) * 4)   // 73728 bytes

template<int MODE>
__global__ __launch_bounds__(256, 2)
void gemm_gru(const float* __restrict__ embs, const float* __restrict__ tags,
              const float* __restrict__ W, const float* __restrict__ bi,
              const float* __restrict__ bh, int M, int Kreal, int nlvl) {
    extern __shared__ float sm[];
    const int tid  = threadIdx.x;
    const int lane = tid & 31;
    const int wid  = tid >> 5;
    const int gID  = lane >> 2, tq = lane & 3;
    const int wmRow = (wid >> 2) * 32;     // 0 / 32
    const int wk    = (wid & 3) * 16;      // k-slice within 64 gate cols
    const int gk0   = blockIdx.x * 64;     // gate-col base
    const int bm    = blockIdx.y * 64;

    float acc[2][6][4];
    #pragma unroll
    for (int a = 0; a < 2; a++)
        #pragma unroll
        for (int b = 0; b < 6; b++)
            #pragma unroll
            for (int c = 0; c < 4; c++) acc[a][b][c] = 0.0f;

    const int NC = (Kreal + BK - 1) / BK;
    const float4 z4 = make_float4(0.f, 0.f, 0.f, 0.f);
    float4 av[2], bv[6];

    // ---- per-thread ldmatrix base addresses (byte offsets into smem) ----
    const uint32_t smem_base = smem_u32(sm);
    // A: matrices {rows 0-7|8-15} x {cols 0-3|4-7}: row = lane&15, coloff = (lane>>4)*4
    uint32_t aAddr[2];
    #pragma unroll
    for (int mt = 0; mt < 2; mt++)
        aAddr[mt] = smem_base + 4u * ((wmRow + mt * 16 + (lane & 15)) * AST + (lane >> 4) * 4);
    // B: matrices {b0 n0|b1 n0|b0 n0+8|b1 n0+8}: row = ((lane>>4)<<3)+(lane&7), coloff = ((lane>>3)&1)*4
    uint32_t bAddr[3];
    #pragma unroll
    for (int g = 0; g < 3; g++)
        bAddr[g] = smem_base + 4u * (2 * TA +
                   (g * 64 + wk + ((lane >> 4) << 3) + (lane & 7)) * AST + ((lane >> 3) & 1) * 4);

    auto loadA = [&](int kc) {
        #pragma unroll
        for (int it = 0; it < 2; it++) {
            int idx = tid + it * 256;
            int r = idx >> 3, cq = (idx & 7) * 4;
            int gm = bm + r, c4 = kc * BK + cq;
            float4 v = z4;
            if (MODE == 0) {
                if (gm < M) {
                    if (c4 < WORD)
                        v = *reinterpret_cast<const float4*>(embs + (size_t)gm * WORD + c4);
                    else if (c4 < LEAF_IN)
                        v = *reinterpret_cast<const float4*>(tags + (size_t)(LEAVES - 1 + gm) * TAG + (c4 - WORD));
                }
            } else if (MODE == 1) {
                if (gm < M) {
                    int pid = (gm >> 1) + nlvl - 1;
                    int ch  = 2 * pid + 1 + (gm & 1);
                    if (c4 < MEM)
                        v = *reinterpret_cast<const float4*>(g_states + (size_t)ch * MEM + c4);
                    else if (c4 < MEM + TAG)
                        v = *reinterpret_cast<const float4*>(tags + (size_t)ch * TAG + (c4 - MEM));
                    else if (c4 < CH_IN)
                        v = *reinterpret_cast<const float4*>(tags + (size_t)pid * TAG + (c4 - MEM - TAG));
                }
            } else {
                const float* src = (MODE == 2) ? g_H : g_H2;
                if (gm < M && c4 < MEM)
                    v = *reinterpret_cast<const float4*>(src + (size_t)gm * MEM + c4);
            }
            av[it] = v;
        }
    };
    auto loadB = [&](int kc) {
        #pragma unroll
        for (int it = 0; it < 6; it++) {
            int idx = tid + it * 256;
            int r = idx >> 3, cq = (idx & 7) * 4;
            int grow = (r >> 6) * MEM + gk0 + (r & 63);
            int c4 = kc * BK + cq;
            bv[it] = (c4 < Kreal)
                ? *reinterpret_cast<const float4*>(W + (size_t)grow * Kreal + c4) : z4;
        }
    };
    auto storeA = [&](int buf) {
        float* base = sm + buf * TA;
        #pragma unroll
        for (int it = 0; it < 2; it++) {
            int idx = tid + it * 256;
            float* d = base + (idx >> 3) * AST + (idx & 7) * 4;
            d[0] = __uint_as_float(f2tf32(av[it].x));
            d[1] = __uint_as_float(f2tf32(av[it].y));
            d[2] = __uint_as_float(f2tf32(av[it].z));
            d[3] = __uint_as_float(f2tf32(av[it].w));
        }
    };
    auto storeB = [&](int buf) {
        float* base = sm + 2 * TA + buf * TB;
        #pragma unroll
        for (int it = 0; it < 6; it++) {
            int idx = tid + it * 256;
            float* d = base + (idx >> 3) * AST + (idx & 7) * 4;
            d[0] = __uint_as_float(f2tf32(bv[it].x));
            d[1] = __uint_as_float(f2tf32(bv[it].y));
            d[2] = __uint_as_float(f2tf32(bv[it].z));
            d[3] = __uint_as_float(f2tf32(bv[it].w));
        }
    };

    loadA(0); loadB(0); storeA(0); storeB(0);
    __syncthreads();

    for (int kc = 0; kc < NC; kc++) {
        const int cur = kc & 1;
        if (kc + 1 < NC) { loadA(kc + 1); loadB(kc + 1); }
        const uint32_t aOff = cur * (TA * 4u);
        const uint32_t bOff = cur * (TB * 4u);
        #pragma unroll
        for (int k8 = 0; k8 < 4; k8++) {
            const uint32_t kb = k8 * 32u;   // 8 floats = 32 bytes
            uint32_t afr[2][4], bfr[3][4];
            #pragma unroll
            for (int mt = 0; mt < 2; mt++) ldsm4(afr[mt], aAddr[mt] + aOff + kb);
            #pragma unroll
            for (int g = 0; g < 3; g++)    ldsm4(bfr[g], bAddr[g] + bOff + kb);
            #pragma unroll
            for (int mt = 0; mt < 2; mt++)
                #pragma unroll
                for (int g = 0; g < 3; g++) {
                    mma_tf32(acc[mt][2 * g],     afr[mt], bfr[g]);       // kt=0 (b0,b1)
                    mma_tf32(acc[mt][2 * g + 1], afr[mt], bfr[g] + 2);   // kt=1
                }
        }
        if (kc + 1 < NC) { storeA(1 - cur); storeB(1 - cur); }
        __syncthreads();
    }

    // ---- fused epilogue: gate math per (row, kcol) ----
    #pragma unroll
    for (int mt = 0; mt < 2; mt++) {
        #pragma unroll
        for (int kt = 0; kt < 2; kt++) {
            #pragma unroll
            for (int j = 0; j < 4; j++) {
                int row = bm + wmRow + mt * 16 + gID + (j >> 1) * 8;
                if (row >= M) continue;
                int kcol = gk0 + wk + kt * 8 + 2 * tq + (j & 1);
                float aR = acc[mt][kt][j];
                float aZ = acc[mt][2 + kt][j];
                float aN = acc[mt][4 + kt][j];
                if (MODE == 0) {
                    float r  = sigmoidf(aR + bi[kcol] + bh[kcol]);
                    float z  = sigmoidf(aZ + bi[MEM + kcol] + bh[MEM + kcol]);
                    float nn = tanhf(aN + bi[2 * MEM + kcol] + r * bh[2 * MEM + kcol]);
                    g_states[(size_t)(LEAVES - 1 + row) * MEM + kcol] = (1.0f - z) * nn;
                } else if (MODE == 1) {
                    float giR = aR + bi[kcol], giZ = aZ + bi[MEM + kcol], giN = aN + bi[2 * MEM + kcol];
                    if ((row & 1) == 0) {
                        float r  = sigmoidf(giR + bh[kcol]);
                        float z  = sigmoidf(giZ + bh[MEM + kcol]);
                        float nn = tanhf(giN + r * bh[2 * MEM + kcol]);
                        g_H[(size_t)(row >> 1) * MEM + kcol] = (1.0f - z) * nn;
                    } else {
                        float* d = g_Gi + (size_t)row * G3;
                        d[kcol] = giR; d[MEM + kcol] = giZ; d[2 * MEM + kcol] = giN;
                    }
                } else if (MODE == 2) {
                    const float* gi = g_Gi + (size_t)(2 * row + 1) * G3;
                    float r  = sigmoidf(gi[kcol] + aR + bh[kcol]);
                    float z  = sigmoidf(gi[MEM + kcol] + aZ + bh[MEM + kcol]);
                    float nn = tanhf(gi[2 * MEM + kcol] + r * (aN + bh[2 * MEM + kcol]));
                    g_H2[(size_t)row * MEM + kcol] =
                        (1.0f - z) * nn + z * g_H[(size_t)row * MEM + kcol];
                } else {
                    float r  = sigmoidf(bi[kcol] + aR + bh[kcol]);
                    float z  = sigmoidf(bi[MEM + kcol] + aZ + bh[MEM + kcol]);
                    float nn = tanhf(bi[2 * MEM + kcol] + r * (aN + bh[2 * MEM + kcol]));
                    g_states[(size_t)(row + nlvl - 1) * MEM + kcol] =
                        (1.0f - z) * nn + z * g_H2[(size_t)row * MEM + kcol];
                }
            }
        }
    }
}

__global__ void copy_out(float* __restrict__ out) {
    int k = blockIdx.x * blockDim.x + threadIdx.x;
    if (k < MEM) out[k] = g_states[k];
}

// ---------------- host driver ------------------------------------------------
extern "C" void kernel_launch(void* const* d_in, const int* in_sizes, int n_in,
                              void* d_out, int out_size) {
    const float* embs    = (const float*)d_in[0];
    const float* tags    = (const float*)d_in[1];
    const float* leaf_Wi = (const float*)d_in[2];
    const float* leaf_bi = (const float*)d_in[4];
    const float* leaf_bh = (const float*)d_in[5];
    const float* node_Wh = (const float*)d_in[7];
    const float* node_bi = (const float*)d_in[8];
    const float* node_bh = (const float*)d_in[9];
    const float* ch_Wi   = (const float*)d_in[10];
    const float* ch_Wh   = (const float*)d_in[11];
    const float* ch_bi   = (const float*)d_in[12];
    const float* ch_bh   = (const float*)d_in[13];

    cudaFuncSetAttribute(gemm_gru<0>, cudaFuncAttributeMaxDynamicSharedMemorySize, SMEM_SZ);
    cudaFuncSetAttribute(gemm_gru<1>, cudaFuncAttributeMaxDynamicSharedMemorySize, SMEM_SZ);
    cudaFuncSetAttribute(gemm_gru<2>, cudaFuncAttributeMaxDynamicSharedMemorySize, SMEM_SZ);
    cudaFuncSetAttribute(gemm_gru<3>, cudaFuncAttributeMaxDynamicSharedMemorySize, SMEM_SZ);

    auto grid = [](int M) { return dim3(MEM / 64, (M + 63) / 64); };

    gemm_gru<0><<<grid(LEAVES), 256, SMEM_SZ>>>(embs, tags, leaf_Wi, leaf_bi, leaf_bh,
                                                LEAVES, LEAF_IN, 0);
    for (int lvl = DEPTH - 1; lvl >= 0; --lvl) {
        int n = 1 << lvl;
        gemm_gru<1><<<grid(2 * n), 256, SMEM_SZ>>>(embs, tags, ch_Wi, ch_bi, ch_bh,
                                                   2 * n, CH_IN, n);
        gemm_gru<2><<<grid(n), 256, SMEM_SZ>>>(embs, tags, ch_Wh, ch_bi, ch_bh,
                                               n, MEM, n);
        gemm_gru<3><<<grid(n), 256, SMEM_SZ>>>(embs, tags, node_Wh, node_bi, node_bh,
                                               n, MEM, n);
    }
    copy_out<<<2, 256>>>((float*)d_out);
}

// round 6
// speedup vs baseline: 2.7183x; 1.0190x over previous
#include <cuda_runtime.h>
#include <cstdint>
#include <math.h>

#define DEPTH   14
#define LEAVES  16384
#define NNODES  32767
#define MEM     512
#define G3      1536
#define WORD    300
#define TAG     100
#define LEAF_IN 400
#define CH_IN   712

// ---------------- scratch (device globals) -----------------------------------
__device__ float g_states[(size_t)NNODES * MEM];
__device__ float g_Gi[(size_t)LEAVES * G3];           // right-child preacts (odd rows)
__device__ float g_H[(size_t)(LEAVES / 2) * MEM];     // h1
__device__ float g_H2[(size_t)(LEAVES / 2) * MEM];    // h2
// tf32-rounded operands
__device__ float g_embsR[(size_t)LEAVES * WORD];
__device__ float g_tagsR[(size_t)NNODES * TAG];
__device__ float g_Wl[(size_t)G3 * LEAF_IN];
__device__ float g_Wci[(size_t)G3 * CH_IN];
__device__ float g_Wch[(size_t)G3 * MEM];
__device__ float g_Wn[(size_t)G3 * MEM];

__device__ __forceinline__ float sigmoidf(float x) { return 1.0f / (1.0f + expf(-x)); }

__device__ __forceinline__ uint32_t f2tf32(float x) {
    uint32_t r;
    asm("cvt.rna.tf32.f32 %0, %1;" : "=r"(r) : "f"(x));
    return r;
}
__device__ __forceinline__ void mma_tf32(float* c, const uint32_t* a, const uint32_t* b) {
    asm volatile(
        "mma.sync.aligned.m16n8k8.row.col.f32.tf32.tf32.f32 "
        "{%0,%1,%2,%3}, {%4,%5,%6,%7}, {%8,%9}, {%0,%1,%2,%3};"
        : "+f"(c[0]), "+f"(c[1]), "+f"(c[2]), "+f"(c[3])
        : "r"(a[0]), "r"(a[1]), "r"(a[2]), "r"(a[3]), "r"(b[0]), "r"(b[1]));
}
__device__ __forceinline__ void ldsm4(uint32_t* r, uint32_t addr) {
    asm volatile("ldmatrix.sync.aligned.m8n8.x4.shared.b16 {%0,%1,%2,%3}, [%4];"
                 : "=r"(r[0]), "=r"(r[1]), "=r"(r[2]), "=r"(r[3]) : "r"(addr));
}
__device__ __forceinline__ uint32_t smem_u32(const void* p) {
    uint32_t a;
    asm("{ .reg .u64 t; cvta.to.shared.u64 t, %1; cvt.u32.u64 %0, t; }" : "=r"(a) : "l"(p));
    return a;
}
__device__ __forceinline__ void cp16(uint32_t dst, const float* src, int sz) {
    asm volatile("cp.async.cg.shared.global [%0], [%1], 16, %2;"
                 :: "r"(dst), "l"(src), "r"(sz) : "memory");
}
#define CP_COMMIT() asm volatile("cp.async.commit_group;" ::: "memory")
#define CP_WAIT1()  asm volatile("cp.async.wait_group 1;" ::: "memory")
#define CP_WAIT0()  asm volatile("cp.async.wait_group 0;" ::: "memory")

// ---------------- prep: round weights/embs/tags to tf32 once -------------------
#define N_EMB (LEAVES * WORD)
#define N_TAG (NNODES * TAG)
#define N_WL  (G3 * LEAF_IN)
#define N_WCI (G3 * CH_IN)
#define N_WCH (G3 * MEM)
#define N_TOT ((int64_t)N_EMB + N_TAG + N_WL + N_WCI + 2 * N_WCH)

__global__ void prep_round(const float* __restrict__ embs, const float* __restrict__ tags,
                           const float* __restrict__ lw, const float* __restrict__ cwi,
                           const float* __restrict__ cwh, const float* __restrict__ nw) {
    int64_t i = blockIdx.x * (int64_t)blockDim.x + threadIdx.x;
    int64_t stride = (int64_t)gridDim.x * blockDim.x;
    for (; i < N_TOT; i += stride) {
        int64_t j = i;
        const float* s; float* d;
        if (j < N_EMB)               { s = embs; d = g_embsR; }
        else if ((j -= N_EMB) < N_TAG) { s = tags; d = g_tagsR; }
        else if ((j -= N_TAG) < N_WL)  { s = lw;   d = g_Wl; }
        else if ((j -= N_WL) < N_WCI)  { s = cwi;  d = g_Wci; }
        else if ((j -= N_WCI) < N_WCH) { s = cwh;  d = g_Wch; }
        else { j -= N_WCH;              s = nw;   d = g_Wn; }
        d[j] = __uint_as_float(f2tf32(s[j]));
    }
}

// ---------------- fused GEMM + GRU-gate kernel ---------------------------------
// 64-row x 64-gate-col tile; B tile = W rows {k, 512+k, 1024+k} (192 rows).
// MODE: 0=leaf, 1=ch_Wi (h1 even / gi odd), 2=ch_Wh (h2), 3=node_Wh (states).
#define AST      36
#define STAGE_B  36864u                 // (64+192)*36*4
#define BOFF     9216u                  // A region = 64*36*4
#define SMEM_SZ  (2 * 36864)

template<int MODE, int K>
__global__ __launch_bounds__(256, 3)
void gemm_gru(const float* __restrict__ Wr, const float* __restrict__ bi,
              const float* __restrict__ bh, int M, int nlvl) {
    extern __shared__ float sm[];
    constexpr int NC = (K + 31) / 32;

    const int tid  = threadIdx.x;
    const int lane = tid & 31;
    const int wid  = tid >> 5;
    const int gID  = lane >> 2, tq = lane & 3;
    const int wmRow = (wid >> 2) * 32;
    const int wk    = (wid & 3) * 16;
    const int gk0   = blockIdx.x * 64;
    const int bm    = blockIdx.y * 64;

    float acc[2][6][4];
    #pragma unroll
    for (int a = 0; a < 2; a++)
        #pragma unroll
        for (int b = 0; b < 6; b++)
            #pragma unroll
            for (int c = 0; c < 4; c++) acc[a][b][c] = 0.0f;

    const uint32_t smem_base = smem_u32(sm);

    // ---- cp.async source/dest precompute ----
    const int rA0 = tid >> 3;                  // 0..31
    const int cq  = (tid & 7) * 4;             // 0..28
    uint32_t dstA0 = smem_base + 4u * (rA0 * AST + cq);   // it stride +4608
    uint32_t dstB0 = smem_base + BOFF + 4u * (rA0 * AST + cq);
    uint32_t offB[6];
    #pragma unroll
    for (int it = 0; it < 6; it++) {
        int rB = rA0 + 32 * it;                // 0..223
        int grow = (rB >> 6) * MEM + gk0 + (rB & 63);
        offB[it] = (uint32_t)grow * K + cq;
    }

    // ---- ldmatrix base addresses ----
    uint32_t aAddr[2];
    #pragma unroll
    for (int mt = 0; mt < 2; mt++)
        aAddr[mt] = smem_base + 4u * ((wmRow + mt * 16 + (lane & 15)) * AST + (lane >> 4) * 4);
    uint32_t bAddr[3];
    #pragma unroll
    for (int g = 0; g < 3; g++)
        bAddr[g] = smem_base + BOFF +
                   4u * ((g * 64 + wk + ((lane >> 4) << 3) + (lane & 7)) * AST + ((lane >> 3) & 1) * 4);

    auto issueA = [&](int kc, uint32_t stN) {
        #pragma unroll
        for (int it = 0; it < 2; it++) {
            const int c4 = kc * 32 + cq;
            const int gm = bm + rA0 + 32 * it;
            const float* p = g_embsR;
            int sz = 0;
            if (MODE == 0) {
                if (gm < M) {
                    if (c4 < WORD)         { p = g_embsR + (size_t)gm * WORD + c4; sz = 16; }
                    else if (c4 < LEAF_IN) { p = g_tagsR + (size_t)(LEAVES - 1 + gm) * TAG + (c4 - WORD); sz = 16; }
                }
            } else if (MODE == 1) {
                if (gm < M) {
                    int pid = (gm >> 1) + nlvl - 1;
                    int ch  = 2 * pid + 1 + (gm & 1);
                    if (c4 < MEM)            { p = g_states + (size_t)ch * MEM + c4; sz = 16; }
                    else if (c4 < MEM + TAG) { p = g_tagsR + (size_t)ch * TAG + (c4 - MEM); sz = 16; }
                    else if (c4 < CH_IN)     { p = g_tagsR + (size_t)pid * TAG + (c4 - MEM - TAG); sz = 16; }
                }
            } else {
                const float* src = (MODE == 2) ? g_H : g_H2;
                if (gm < M && c4 < MEM) { p = src + (size_t)gm * MEM + c4; sz = 16; }
            }
            cp16(dstA0 + stN + it * 4608u, p, sz);
        }
    };
    auto issueB = [&](int kc, uint32_t stN) {
        const int c4 = kc * 32 + cq;
        const int sz = (c4 < K) ? 16 : 0;
        #pragma unroll
        for (int it = 0; it < 6; it++)
            cp16(dstB0 + stN + it * 4608u, Wr + offB[it] + (uint32_t)kc * 32u, sz);
    };

    // ---- pipeline: 2-stage cp.async double buffer ----
    issueA(0, 0); issueB(0, 0); CP_COMMIT();

    #pragma unroll 2
    for (int kc = 0; kc < NC; kc++) {
        if (kc + 1 < NC) {
            const uint32_t stN = ((kc + 1) & 1) ? STAGE_B : 0u;
            issueA(kc + 1, stN); issueB(kc + 1, stN); CP_COMMIT();
            CP_WAIT1();
        } else {
            CP_WAIT0();
        }
        __syncthreads();
        const uint32_t stC = (kc & 1) ? STAGE_B : 0u;
        #pragma unroll
        for (int k8 = 0; k8 < 4; k8++) {
            const uint32_t kb = stC + k8 * 32u;
            uint32_t afr[2][4], bfr[3][4];
            ldsm4(afr[0], aAddr[0] + kb);
            ldsm4(afr[1], aAddr[1] + kb);
            ldsm4(bfr[0], bAddr[0] + kb);
            ldsm4(bfr[1], bAddr[1] + kb);
            ldsm4(bfr[2], bAddr[2] + kb);
            #pragma unroll
            for (int mt = 0; mt < 2; mt++)
                #pragma unroll
                for (int g = 0; g < 3; g++) {
                    mma_tf32(acc[mt][2 * g],     afr[mt], bfr[g]);
                    mma_tf32(acc[mt][2 * g + 1], afr[mt], bfr[g] + 2);
                }
        }
        __syncthreads();
    }

    // ---- fused epilogue: gate math per (row, kcol) ----
    #pragma unroll
    for (int mt = 0; mt < 2; mt++) {
        #pragma unroll
        for (int kt = 0; kt < 2; kt++) {
            #pragma unroll
            for (int j = 0; j < 4; j++) {
                int row = bm + wmRow + mt * 16 + gID + (j >> 1) * 8;
                if (row >= M) continue;
                int kcol = gk0 + wk + kt * 8 + 2 * tq + (j & 1);
                float aR = acc[mt][kt][j];
                float aZ = acc[mt][2 + kt][j];
                float aN = acc[mt][4 + kt][j];
                if (MODE == 0) {
                    float r  = sigmoidf(aR + bi[kcol] + bh[kcol]);
                    float z  = sigmoidf(aZ + bi[MEM + kcol] + bh[MEM + kcol]);
                    float nn = tanhf(aN + bi[2 * MEM + kcol] + r * bh[2 * MEM + kcol]);
                    g_states[(size_t)(LEAVES - 1 + row) * MEM + kcol] = (1.0f - z) * nn;
                } else if (MODE == 1) {
                    float giR = aR + bi[kcol], giZ = aZ + bi[MEM + kcol], giN = aN + bi[2 * MEM + kcol];
                    if ((row & 1) == 0) {
                        float r  = sigmoidf(giR + bh[kcol]);
                        float z  = sigmoidf(giZ + bh[MEM + kcol]);
                        float nn = tanhf(giN + r * bh[2 * MEM + kcol]);
                        g_H[(size_t)(row >> 1) * MEM + kcol] = (1.0f - z) * nn;
                    } else {
                        float* d = g_Gi + (size_t)row * G3;
                        d[kcol] = giR; d[MEM + kcol] = giZ; d[2 * MEM + kcol] = giN;
                    }
                } else if (MODE == 2) {
                    const float* gi = g_Gi + (size_t)(2 * row + 1) * G3;
                    float r  = sigmoidf(gi[kcol] + aR + bh[kcol]);
                    float z  = sigmoidf(gi[MEM + kcol] + aZ + bh[MEM + kcol]);
                    float nn = tanhf(gi[2 * MEM + kcol] + r * (aN + bh[2 * MEM + kcol]));
                    g_H2[(size_t)row * MEM + kcol] =
                        (1.0f - z) * nn + z * g_H[(size_t)row * MEM + kcol];
                } else {
                    float r  = sigmoidf(bi[kcol] + aR + bh[kcol]);
                    float z  = sigmoidf(bi[MEM + kcol] + aZ + bh[MEM + kcol]);
                    float nn = tanhf(bi[2 * MEM + kcol] + r * (aN + bh[2 * MEM + kcol]));
                    g_states[(size_t)(row + nlvl - 1) * MEM + kcol] =
                        (1.0f - z) * nn + z * g_H2[(size_t)row * MEM + kcol];
                }
            }
        }
    }
}

__global__ void copy_out(float* __restrict__ out) {
    int k = blockIdx.x * blockDim.x + threadIdx.x;
    if (k < MEM) out[k] = g_states[k];
}

// ---------------- host driver ------------------------------------------------
extern "C" void kernel_launch(void* const* d_in, const int* in_sizes, int n_in,
                              void* d_out, int out_size) {
    const float* embs    = (const float*)d_in[0];
    const float* tags    = (const float*)d_in[1];
    const float* leaf_Wi = (const float*)d_in[2];
    const float* leaf_bi = (const float*)d_in[4];
    const float* leaf_bh = (const float*)d_in[5];
    const float* node_Wh = (const float*)d_in[7];
    const float* node_bi = (const float*)d_in[8];
    const float* node_bh = (const float*)d_in[9];
    const float* ch_Wi   = (const float*)d_in[10];
    const float* ch_Wh   = (const float*)d_in[11];
    const float* ch_bi   = (const float*)d_in[12];
    const float* ch_bh   = (const float*)d_in[13];

    float *pWl, *pWci, *pWch, *pWn;
    cudaGetSymbolAddress((void**)&pWl,  g_Wl);
    cudaGetSymbolAddress((void**)&pWci, g_Wci);
    cudaGetSymbolAddress((void**)&pWch, g_Wch);
    cudaGetSymbolAddress((void**)&pWn,  g_Wn);

    cudaFuncSetAttribute(gemm_gru<0,LEAF_IN>, cudaFuncAttributeMaxDynamicSharedMemorySize, SMEM_SZ);
    cudaFuncSetAttribute(gemm_gru<1,CH_IN>,   cudaFuncAttributeMaxDynamicSharedMemorySize, SMEM_SZ);
    cudaFuncSetAttribute(gemm_gru<2,MEM>,     cudaFuncAttributeMaxDynamicSharedMemorySize, SMEM_SZ);
    cudaFuncSetAttribute(gemm_gru<3,MEM>,     cudaFuncAttributeMaxDynamicSharedMemorySize, SMEM_SZ);

    auto grid = [](int M) { return dim3(MEM / 64, (M + 63) / 64); };

    prep_round<<<2048, 256>>>(embs, tags, leaf_Wi, ch_Wi, ch_Wh, node_Wh);

    gemm_gru<0,LEAF_IN><<<grid(LEAVES), 256, SMEM_SZ>>>(pWl, leaf_bi, leaf_bh, LEAVES, 0);
    for (int lvl = DEPTH - 1; lvl >= 0; --lvl) {
        int n = 1 << lvl;
        gemm_gru<1,CH_IN><<<grid(2 * n), 256, SMEM_SZ>>>(pWci, ch_bi, ch_bh, 2 * n, n);
        gemm_gru<2,MEM><<<grid(n), 256, SMEM_SZ>>>(pWch, ch_bi, ch_bh, n, n);
        gemm_gru<3,MEM><<<grid(n), 256, SMEM_SZ>>>(pWn, node_bi, node_bh, n, n);
    }
    copy_out<<<2, 256>>>((float*)d_out);
}

// round 7
// speedup vs baseline: 3.1697x; 1.1661x over previous
#include <cuda_runtime.h>
#include <cstdint>
#include <math.h>

#define DEPTH   14
#define LEAVES  16384
#define NNODES  32767
#define MEM     512
#define G3      1536
#define WORD    300
#define TAG     100
#define LEAF_IN 400
#define CH_IN   712

// ---------------- scratch (device globals) -----------------------------------
__device__ float g_states[(size_t)NNODES * MEM];
__device__ float g_Gi[(size_t)LEAVES * G3];           // right-child preacts (odd rows)
__device__ float g_H[(size_t)(LEAVES / 2) * MEM];     // h1
__device__ float g_H2[(size_t)(LEAVES / 2) * MEM];    // h2
// tf32-rounded operands
__device__ float g_embsR[(size_t)LEAVES * WORD];
__device__ float g_tagsR[(size_t)NNODES * TAG];
__device__ float g_Wl[(size_t)G3 * LEAF_IN];
__device__ float g_Wci[(size_t)G3 * CH_IN];
__device__ float g_Wch[(size_t)G3 * MEM];
__device__ float g_Wn[(size_t)G3 * MEM];

__device__ __forceinline__ float sigmoidf(float x) { return 1.0f / (1.0f + expf(-x)); }

__device__ __forceinline__ uint32_t f2tf32(float x) {
    uint32_t r;
    asm("cvt.rna.tf32.f32 %0, %1;" : "=r"(r) : "f"(x));
    return r;
}
__device__ __forceinline__ void mma_tf32(float* c, const uint32_t* a, const uint32_t* b) {
    asm volatile(
        "mma.sync.aligned.m16n8k8.row.col.f32.tf32.tf32.f32 "
        "{%0,%1,%2,%3}, {%4,%5,%6,%7}, {%8,%9}, {%0,%1,%2,%3};"
        : "+f"(c[0]), "+f"(c[1]), "+f"(c[2]), "+f"(c[3])
        : "r"(a[0]), "r"(a[1]), "r"(a[2]), "r"(a[3]), "r"(b[0]), "r"(b[1]));
}
__device__ __forceinline__ void ldsm4(uint32_t* r, uint32_t addr) {
    asm volatile("ldmatrix.sync.aligned.m8n8.x4.shared.b16 {%0,%1,%2,%3}, [%4];"
                 : "=r"(r[0]), "=r"(r[1]), "=r"(r[2]), "=r"(r[3]) : "r"(addr));
}
__device__ __forceinline__ uint32_t smem_u32(const void* p) {
    uint32_t a;
    asm("{ .reg .u64 t; cvta.to.shared.u64 t, %1; cvt.u32.u64 %0, t; }" : "=r"(a) : "l"(p));
    return a;
}
__device__ __forceinline__ void cp16(uint32_t dst, const float* src, int sz) {
    asm volatile("cp.async.cg.shared.global [%0], [%1], 16, %2;"
                 :: "r"(dst), "l"(src), "r"(sz) : "memory");
}
#define CP_COMMIT() asm volatile("cp.async.commit_group;" ::: "memory")
#define CP_WAIT1()  asm volatile("cp.async.wait_group 1;" ::: "memory")

// ---------------- prep: round weights/embs/tags to tf32 once -------------------
#define N_EMB (LEAVES * WORD)
#define N_TAG (NNODES * TAG)
#define N_WL  (G3 * LEAF_IN)
#define N_WCI (G3 * CH_IN)
#define N_WCH (G3 * MEM)
#define N_TOT ((int64_t)N_EMB + N_TAG + N_WL + N_WCI + 2 * N_WCH)

__global__ void prep_round(const float* __restrict__ embs, const float* __restrict__ tags,
                           const float* __restrict__ lw, const float* __restrict__ cwi,
                           const float* __restrict__ cwh, const float* __restrict__ nw) {
    int64_t i = blockIdx.x * (int64_t)blockDim.x + threadIdx.x;
    int64_t stride = (int64_t)gridDim.x * blockDim.x;
    for (; i < N_TOT; i += stride) {
        int64_t j = i;
        const float* s; float* d;
        if (j < N_EMB)               { s = embs; d = g_embsR; }
        else if ((j -= N_EMB) < N_TAG) { s = tags; d = g_tagsR; }
        else if ((j -= N_TAG) < N_WL)  { s = lw;   d = g_Wl; }
        else if ((j -= N_WL) < N_WCI)  { s = cwi;  d = g_Wci; }
        else if ((j -= N_WCI) < N_WCH) { s = cwh;  d = g_Wch; }
        else { j -= N_WCH;              s = nw;   d = g_Wn; }
        d[j] = __uint_as_float(f2tf32(s[j]));
    }
}

// ---------------- fused GEMM + GRU-gate kernel ---------------------------------
// 64-row x 64-gate-col tile; B tile = W rows {k, 512+k, 1024+k} (192 rows).
// MODE: 0=leaf, 1=ch_Wi (h1 even / gi odd), 2=ch_Wh (h2), 3=node_Wh (states).
#define AST      36
#define STAGE_B  36864u                 // (64+192)*36*4
#define BOFF     9216u                  // A region = 64*36*4
#define NSTAGE   3
#define SMEM_SZ  (NSTAGE * 36864)

template<int MODE, int K>
__global__ __launch_bounds__(256, 2)
void gemm_gru(const float* __restrict__ Wr, const float* __restrict__ bi,
              const float* __restrict__ bh, int M, int nlvl, float* __restrict__ out) {
    extern __shared__ float sm[];
    constexpr int NC = (K + 31) / 32;

    const int tid  = threadIdx.x;
    const int lane = tid & 31;
    const int wid  = tid >> 5;
    const int gID  = lane >> 2, tq = lane & 3;
    const int wmRow = (wid >> 2) * 32;
    const int wk    = (wid & 3) * 16;
    const int gk0   = blockIdx.x * 64;
    const int bm    = blockIdx.y * 64;

    float acc[2][6][4];
    #pragma unroll
    for (int a = 0; a < 2; a++)
        #pragma unroll
        for (int b = 0; b < 6; b++)
            #pragma unroll
            for (int c = 0; c < 4; c++) acc[a][b][c] = 0.0f;

    const uint32_t smem_base = smem_u32(sm);

    // ---- cp.async source/dest precompute ----
    const int rA0 = tid >> 3;                  // 0..31
    const int cq  = (tid & 7) * 4;             // 0..28
    uint32_t dstA0 = smem_base + 4u * (rA0 * AST + cq);
    uint32_t dstB0 = smem_base + BOFF + 4u * (rA0 * AST + cq);
    uint32_t offB[6];
    #pragma unroll
    for (int it = 0; it < 6; it++) {
        int rB = rA0 + 32 * it;                // 0..223
        int grow = (rB >> 6) * MEM + gk0 + (rB & 63);
        offB[it] = (uint32_t)grow * K + cq;
    }

    // ---- ldmatrix base addresses ----
    uint32_t aAddr[2];
    #pragma unroll
    for (int mt = 0; mt < 2; mt++)
        aAddr[mt] = smem_base + 4u * ((wmRow + mt * 16 + (lane & 15)) * AST + (lane >> 4) * 4);
    uint32_t bAddr[3];
    #pragma unroll
    for (int g = 0; g < 3; g++)
        bAddr[g] = smem_base + BOFF +
                   4u * ((g * 64 + wk + ((lane >> 4) << 3) + (lane & 7)) * AST + ((lane >> 3) & 1) * 4);

    auto issueA = [&](int kc, uint32_t stN) {
        #pragma unroll
        for (int it = 0; it < 2; it++) {
            const int c4 = kc * 32 + cq;
            const int gm = bm + rA0 + 32 * it;
            const float* p = g_embsR;
            int sz = 0;
            if (MODE == 0) {
                if (gm < M) {
                    if (c4 < WORD)         { p = g_embsR + (size_t)gm * WORD + c4; sz = 16; }
                    else if (c4 < LEAF_IN) { p = g_tagsR + (size_t)(LEAVES - 1 + gm) * TAG + (c4 - WORD); sz = 16; }
                }
            } else if (MODE == 1) {
                if (gm < M) {
                    int pid = (gm >> 1) + nlvl - 1;
                    int ch  = 2 * pid + 1 + (gm & 1);
                    if (c4 < MEM)            { p = g_states + (size_t)ch * MEM + c4; sz = 16; }
                    else if (c4 < MEM + TAG) { p = g_tagsR + (size_t)ch * TAG + (c4 - MEM); sz = 16; }
                    else if (c4 < CH_IN)     { p = g_tagsR + (size_t)pid * TAG + (c4 - MEM - TAG); sz = 16; }
                }
            } else {
                const float* src = (MODE == 2) ? g_H : g_H2;
                if (gm < M && c4 < MEM) { p = src + (size_t)gm * MEM + c4; sz = 16; }
            }
            cp16(dstA0 + stN + it * 4608u, p, sz);
        }
    };
    auto issueB = [&](int kc, uint32_t stN) {
        const int c4 = kc * 32 + cq;
        const int sz = (c4 < K) ? 16 : 0;
        #pragma unroll
        for (int it = 0; it < 6; it++)
            cp16(dstB0 + stN + it * 4608u, Wr + offB[it] + (uint32_t)kc * 32u, sz);
    };

    // ---- 3-stage pipeline, one __syncthreads per iteration ----
    issueA(0, 0); issueB(0, 0); CP_COMMIT();
    if (NC > 1) { issueA(1, STAGE_B); issueB(1, STAGE_B); }
    CP_COMMIT();

    #pragma unroll
    for (int kc = 0; kc < NC; kc++) {
        CP_WAIT1();                       // group kc complete (empty groups count too)
        __syncthreads();                  // everyone sees stage kc; buffer (kc+2)%3 free
        if (kc + 2 < NC) {
            const uint32_t stN = (uint32_t)((kc + 2) % NSTAGE) * STAGE_B;
            issueA(kc + 2, stN); issueB(kc + 2, stN);
        }
        CP_COMMIT();
        const uint32_t stC = (uint32_t)(kc % NSTAGE) * STAGE_B;
        #pragma unroll
        for (int k8 = 0; k8 < 4; k8++) {
            const uint32_t kb = stC + k8 * 32u;
            uint32_t afr[2][4], bfr[3][4];
            ldsm4(afr[0], aAddr[0] + kb);
            ldsm4(afr[1], aAddr[1] + kb);
            ldsm4(bfr[0], bAddr[0] + kb);
            ldsm4(bfr[1], bAddr[1] + kb);
            ldsm4(bfr[2], bAddr[2] + kb);
            #pragma unroll
            for (int mt = 0; mt < 2; mt++)
                #pragma unroll
                for (int g = 0; g < 3; g++) {
                    mma_tf32(acc[mt][2 * g],     afr[mt], bfr[g]);
                    mma_tf32(acc[mt][2 * g + 1], afr[mt], bfr[g] + 2);
                }
        }
    }

    // ---- fused epilogue: gate math per (row, kcol) ----
    #pragma unroll
    for (int mt = 0; mt < 2; mt++) {
        #pragma unroll
        for (int kt = 0; kt < 2; kt++) {
            #pragma unroll
            for (int j = 0; j < 4; j++) {
                int row = bm + wmRow + mt * 16 + gID + (j >> 1) * 8;
                if (row >= M) continue;
                int kcol = gk0 + wk + kt * 8 + 2 * tq + (j & 1);
                float aR = acc[mt][kt][j];
                float aZ = acc[mt][2 + kt][j];
                float aN = acc[mt][4 + kt][j];
                if (MODE == 0) {
                    float r  = sigmoidf(aR + bi[kcol] + bh[kcol]);
                    float z  = sigmoidf(aZ + bi[MEM + kcol] + bh[MEM + kcol]);
                    float nn = tanhf(aN + bi[2 * MEM + kcol] + r * bh[2 * MEM + kcol]);
                    g_states[(size_t)(LEAVES - 1 + row) * MEM + kcol] = (1.0f - z) * nn;
                } else if (MODE == 1) {
                    float giR = aR + bi[kcol], giZ = aZ + bi[MEM + kcol], giN = aN + bi[2 * MEM + kcol];
                    if ((row & 1) == 0) {
                        float r  = sigmoidf(giR + bh[kcol]);
                        float z  = sigmoidf(giZ + bh[MEM + kcol]);
                        float nn = tanhf(giN + r * bh[2 * MEM + kcol]);
                        g_H[(size_t)(row >> 1) * MEM + kcol] = (1.0f - z) * nn;
                    } else {
                        float* d = g_Gi + (size_t)row * G3;
                        d[kcol] = giR; d[MEM + kcol] = giZ; d[2 * MEM + kcol] = giN;
                    }
                } else if (MODE == 2) {
                    const float* gi = g_Gi + (size_t)(2 * row + 1) * G3;
                    float r  = sigmoidf(gi[kcol] + aR + bh[kcol]);
                    float z  = sigmoidf(gi[MEM + kcol] + aZ + bh[MEM + kcol]);
                    float nn = tanhf(gi[2 * MEM + kcol] + r * (aN + bh[2 * MEM + kcol]));
                    g_H2[(size_t)row * MEM + kcol] =
                        (1.0f - z) * nn + z * g_H[(size_t)row * MEM + kcol];
                } else {
                    float r  = sigmoidf(bi[kcol] + aR + bh[kcol]);
                    float z  = sigmoidf(bi[MEM + kcol] + aZ + bh[MEM + kcol]);
                    float nn = tanhf(bi[2 * MEM + kcol] + r * (aN + bh[2 * MEM + kcol]));
                    float st = (1.0f - z) * nn + z * g_H2[(size_t)row * MEM + kcol];
                    g_states[(size_t)(row + nlvl - 1) * MEM + kcol] = st;
                    if (nlvl == 1) out[kcol] = st;   // root level: write output directly
                }
            }
        }
    }
}

// ---------------- host driver ------------------------------------------------
extern "C" void kernel_launch(void* const* d_in, const int* in_sizes, int n_in,
                              void* d_out, int out_size) {
    const float* embs    = (const float*)d_in[0];
    const float* tags    = (const float*)d_in[1];
    const float* leaf_Wi = (const float*)d_in[2];
    const float* leaf_bi = (const float*)d_in[4];
    const float* leaf_bh = (const float*)d_in[5];
    const float* node_Wh = (const float*)d_in[7];
    const float* node_bi = (const float*)d_in[8];
    const float* node_bh = (const float*)d_in[9];
    const float* ch_Wi   = (const float*)d_in[10];
    const float* ch_Wh   = (const float*)d_in[11];
    const float* ch_bi   = (const float*)d_in[12];
    const float* ch_bh   = (const float*)d_in[13];

    float *pWl, *pWci, *pWch, *pWn;
    cudaGetSymbolAddress((void**)&pWl,  g_Wl);
    cudaGetSymbolAddress((void**)&pWci, g_Wci);
    cudaGetSymbolAddress((void**)&pWch, g_Wch);
    cudaGetSymbolAddress((void**)&pWn,  g_Wn);

    cudaFuncSetAttribute(gemm_gru<0,LEAF_IN>, cudaFuncAttributeMaxDynamicSharedMemorySize, SMEM_SZ);
    cudaFuncSetAttribute(gemm_gru<1,CH_IN>,   cudaFuncAttributeMaxDynamicSharedMemorySize, SMEM_SZ);
    cudaFuncSetAttribute(gemm_gru<2,MEM>,     cudaFuncAttributeMaxDynamicSharedMemorySize, SMEM_SZ);
    cudaFuncSetAttribute(gemm_gru<3,MEM>,     cudaFuncAttributeMaxDynamicSharedMemorySize, SMEM_SZ);

    auto grid = [](int M) { return dim3(MEM / 64, (M + 63) / 64); };
    float* out = (float*)d_out;

    prep_round<<<2048, 256>>>(embs, tags, leaf_Wi, ch_Wi, ch_Wh, node_Wh);

    gemm_gru<0,LEAF_IN><<<grid(LEAVES), 256, SMEM_SZ>>>(pWl, leaf_bi, leaf_bh, LEAVES, 0, out);
    for (int lvl = DEPTH - 1; lvl >= 0; --lvl) {
        int n = 1 << lvl;
        gemm_gru<1,CH_IN><<<grid(2 * n), 256, SMEM_SZ>>>(pWci, ch_bi, ch_bh, 2 * n, n, out);
        gemm_gru<2,MEM><<<grid(n), 256, SMEM_SZ>>>(pWch, ch_bi, ch_bh, n, n, out);
        gemm_gru<3,MEM><<<grid(n), 256, SMEM_SZ>>>(pWn, node_bi, node_bh, n, n, out);
    }
}